// round 6
// baseline (speedup 1.0000x reference)
#include <cuda_runtime.h>
#include <math.h>

#define N_NODES 50000
#define N_EDGES 800000
#define DIM 64
#define FT 128   // nodes per FFN block
#define NP 196   // ceil(N_NODES / 256)

typedef unsigned long long u64;

__device__ __forceinline__ u64 pack2(float lo, float hi) {
    u64 d;
    asm("mov.b64 %0, {%1, %2};"
        : "=l"(d) : "r"(__float_as_uint(lo)), "r"(__float_as_uint(hi)));
    return d;
}
__device__ __forceinline__ float2 unpack2(u64 v) {
    unsigned lo, hi;
    asm("mov.b64 {%0, %1}, %2;" : "=r"(lo), "=r"(hi) : "l"(v));
    return make_float2(__uint_as_float(lo), __uint_as_float(hi));
}
#define FMA2(d, a, b) asm("fma.rn.f32x2 %0, %1, %2, %0;" : "+l"(d) : "l"(a), "l"(b))

// Scratch (device globals)
__device__ int    g_out_cnt[N_NODES];
__device__ int    g_in_cnt[N_NODES];
__device__ int    g_row_start[N_NODES];
__device__ int    g_cursor[N_NODES];
__device__ float2 g_edata[N_EDGES];     // (src_idx bits, rsqrt(out_deg[src]))
__device__ float  g_agg[(size_t)N_NODES * DIM];

// ---------------------------------------------------------------------------
// 0) Zero counters
// ---------------------------------------------------------------------------
__global__ void zero_kernel() {
    int i = blockIdx.x * blockDim.x + threadIdx.x;
    if (i < N_NODES) {
        g_out_cnt[i] = 0;
        g_in_cnt[i]  = 0;
    }
}

// ---------------------------------------------------------------------------
// 1) Histogram (int4: 4 edges per thread)
// ---------------------------------------------------------------------------
__global__ void hist_kernel(const int* __restrict__ src,
                            const int* __restrict__ dst) {
    int i4 = blockIdx.x * blockDim.x + threadIdx.x;
    if (i4 < N_EDGES / 4) {
        int4 s = ((const int4*)src)[i4];
        int4 d = ((const int4*)dst)[i4];
        atomicAdd(&g_out_cnt[s.x], 1);
        atomicAdd(&g_out_cnt[s.y], 1);
        atomicAdd(&g_out_cnt[s.z], 1);
        atomicAdd(&g_out_cnt[s.w], 1);
        atomicAdd(&g_in_cnt[d.x], 1);
        atomicAdd(&g_in_cnt[d.y], 1);
        atomicAdd(&g_in_cnt[d.z], 1);
        atomicAdd(&g_in_cnt[d.w], 1);
    }
}

// ---------------------------------------------------------------------------
// 2) Single-kernel exclusive scan: block b redundantly sums in_cnt[0..256b),
//    then does its local shuffle scan. No cross-block communication.
// ---------------------------------------------------------------------------
__global__ void __launch_bounds__(256) scan_kernel() {
    __shared__ int ws1[8], ws2[8];
    __shared__ int s_base;
    const int t = threadIdx.x, lane = t & 31, w = t >> 5;
    const int b = blockIdx.x;

    // sum of all elements in blocks before b
    int pre = 0;
    for (int i = t; i < b * 256; i += 256) pre += g_in_cnt[i];
    #pragma unroll
    for (int off = 16; off > 0; off >>= 1)
        pre += __shfl_down_sync(0xffffffffu, pre, off);
    if (lane == 0) ws1[w] = pre;
    __syncthreads();
    if (t == 0) {
        int s = 0;
        #pragma unroll
        for (int k = 0; k < 8; k++) s += ws1[k];
        s_base = s;
    }

    // local inclusive shuffle scan
    int i = b * 256 + t;
    int c = (i < N_NODES) ? g_in_cnt[i] : 0;
    int v = c;
    #pragma unroll
    for (int off = 1; off < 32; off <<= 1) {
        int n = __shfl_up_sync(0xffffffffu, v, off);
        if (lane >= off) v += n;
    }
    if (lane == 31) ws2[w] = v;
    __syncthreads();
    if (w == 0 && lane < 8) {
        int s = ws2[lane];
        #pragma unroll
        for (int off = 1; off < 8; off <<= 1) {
            int n = __shfl_up_sync(0x000000ffu, s, off);
            if (lane >= off) s += n;
        }
        ws2[lane] = s;
    }
    __syncthreads();
    if (i < N_NODES) {
        int start = s_base + (v - c) + ((w > 0) ? ws2[w - 1] : 0);
        g_row_start[i] = start;
        g_cursor[i]    = start;
    }
}

// ---------------------------------------------------------------------------
// 3) Fill: edata[cursor[dst]++] = (src, rsqrt(out_deg[src]))  (4 edges/thread)
// ---------------------------------------------------------------------------
__global__ void fill_kernel(const int* __restrict__ src,
                            const int* __restrict__ dst) {
    int i4 = blockIdx.x * blockDim.x + threadIdx.x;
    if (i4 < N_EDGES / 4) {
        int4 s = ((const int4*)src)[i4];
        int4 d = ((const int4*)dst)[i4];
        float rs;
        int pos;
        rs  = rsqrtf((float)__ldg(g_out_cnt + s.x));
        pos = atomicAdd(&g_cursor[d.x], 1);
        g_edata[pos] = make_float2(__int_as_float(s.x), rs);
        rs  = rsqrtf((float)__ldg(g_out_cnt + s.y));
        pos = atomicAdd(&g_cursor[d.y], 1);
        g_edata[pos] = make_float2(__int_as_float(s.y), rs);
        rs  = rsqrtf((float)__ldg(g_out_cnt + s.z));
        pos = atomicAdd(&g_cursor[d.z], 1);
        g_edata[pos] = make_float2(__int_as_float(s.z), rs);
        rs  = rsqrtf((float)__ldg(g_out_cnt + s.w));
        pos = atomicAdd(&g_cursor[d.w], 1);
        g_edata[pos] = make_float2(__int_as_float(s.w), rs);
    }
}

// ---------------------------------------------------------------------------
// 4) Gather-aggregate: warp per dst node, register accumulation, single write.
// ---------------------------------------------------------------------------
__global__ void __launch_bounds__(256) gather_kernel(const float* __restrict__ x) {
    int node = (blockIdx.x * blockDim.x + threadIdx.x) >> 5;
    if (node >= N_NODES) return;
    const int lane = threadIdx.x & 31;

    const int deg   = __ldg(g_in_cnt + node);
    const int start = __ldg(g_row_start + node);
    const int end   = start + deg;

    float acc0 = 0.0f, acc1 = 0.0f;
    int j = start;
    for (; j + 4 <= end; j += 4) {
        float2 e0 = __ldg(g_edata + j);
        float2 e1 = __ldg(g_edata + j + 1);
        float2 e2 = __ldg(g_edata + j + 2);
        float2 e3 = __ldg(g_edata + j + 3);
        const float* p0 = x + (size_t)__float_as_int(e0.x) * DIM;
        const float* p1 = x + (size_t)__float_as_int(e1.x) * DIM;
        const float* p2 = x + (size_t)__float_as_int(e2.x) * DIM;
        const float* p3 = x + (size_t)__float_as_int(e3.x) * DIM;
        acc0 = fmaf(__ldg(p0 + lane),      e0.y, acc0);
        acc1 = fmaf(__ldg(p0 + lane + 32), e0.y, acc1);
        acc0 = fmaf(__ldg(p1 + lane),      e1.y, acc0);
        acc1 = fmaf(__ldg(p1 + lane + 32), e1.y, acc1);
        acc0 = fmaf(__ldg(p2 + lane),      e2.y, acc0);
        acc1 = fmaf(__ldg(p2 + lane + 32), e2.y, acc1);
        acc0 = fmaf(__ldg(p3 + lane),      e3.y, acc0);
        acc1 = fmaf(__ldg(p3 + lane + 32), e3.y, acc1);
    }
    for (; j < end; j++) {
        float2 e0 = __ldg(g_edata + j);
        const float* p0 = x + (size_t)__float_as_int(e0.x) * DIM;
        acc0 = fmaf(__ldg(p0 + lane),      e0.y, acc0);
        acc1 = fmaf(__ldg(p0 + lane + 32), e0.y, acc1);
    }

    float rs_in = (deg > 0) ? rsqrtf((float)deg) : 0.0f;
    g_agg[(size_t)node * DIM + lane]      = acc0 * rs_in;
    g_agg[(size_t)node * DIM + lane + 32] = acc1 * rs_in;
}

// ---------------------------------------------------------------------------
// 5) FFN with packed f32x2 FMA. Block = 128 nodes x 64 cols, 128 threads,
//    8 nodes x 8 cols (= 4 packed col-pairs) per thread.
// ---------------------------------------------------------------------------
__global__ void __launch_bounds__(128) ffn_kernel(const float* __restrict__ w1,
                                                  const float* __restrict__ b1,
                                                  const float* __restrict__ w2,
                                                  const float* __restrict__ b2,
                                                  float* __restrict__ out) {
    __shared__ float sT[DIM * FT];     // [k][node] 32KB, reused for h
    __shared__ float s_w[DIM * DIM];   // 16KB, w1 then w2

    const int tid  = threadIdx.x;
    const int base = blockIdx.x * FT;
    const int tn   = tid & 15;   // node group: nodes 8*tn .. 8*tn+7
    const int tc   = tid >> 4;   // col group:  cols  8*tc .. 8*tc+7

    #pragma unroll
    for (int i = tid; i < DIM * DIM; i += 128) s_w[i] = w1[i];

    // transpose-fill sT
    {
        const int node = base + tid;
        #pragma unroll
        for (int k4 = 0; k4 < 16; k4++) {
            float4 v = make_float4(0.f, 0.f, 0.f, 0.f);
            if (node < N_NODES)
                v = *reinterpret_cast<const float4*>(g_agg + (size_t)node * DIM + k4 * 4);
            sT[(k4 * 4 + 0) * FT + tid] = v.x;
            sT[(k4 * 4 + 1) * FT + tid] = v.y;
            sT[(k4 * 4 + 2) * FT + tid] = v.z;
            sT[(k4 * 4 + 3) * FT + tid] = v.w;
        }
    }
    __syncthreads();

    // ---- GEMM1: h = agg @ w1 + b1  (packed along cols) ----
    u64 acc[8][4];
    {
        float4 bj0 = __ldg((const float4*)(b1 + tc * 8));
        float4 bj1 = __ldg((const float4*)(b1 + tc * 8 + 4));
        u64 bb[4] = {pack2(bj0.x, bj0.y), pack2(bj0.z, bj0.w),
                     pack2(bj1.x, bj1.y), pack2(bj1.z, bj1.w)};
        #pragma unroll
        for (int i = 0; i < 8; i++)
            #pragma unroll
            for (int p = 0; p < 4; p++) acc[i][p] = bb[p];
    }

    #pragma unroll 4
    for (int k = 0; k < DIM; k++) {
        float4 a0 = *reinterpret_cast<const float4*>(&sT[k * FT + tn * 8]);
        float4 a1 = *reinterpret_cast<const float4*>(&sT[k * FT + tn * 8 + 4]);
        const u64* wrow = reinterpret_cast<const u64*>(&s_w[k * DIM + tc * 8]);
        ulonglong2 wp0 = *reinterpret_cast<const ulonglong2*>(wrow);
        ulonglong2 wp1 = *reinterpret_cast<const ulonglong2*>(wrow + 2);
        float a[8] = {a0.x, a0.y, a0.z, a0.w, a1.x, a1.y, a1.z, a1.w};
        #pragma unroll
        for (int i = 0; i < 8; i++) {
            u64 ap = pack2(a[i], a[i]);
            FMA2(acc[i][0], ap, wp0.x);
            FMA2(acc[i][1], ap, wp0.y);
            FMA2(acc[i][2], ap, wp1.x);
            FMA2(acc[i][3], ap, wp1.y);
        }
    }

    // exact GELU (unpack)
    float hf[8][8];
    const float inv_sqrt2 = 0.70710678118654752f;
    #pragma unroll
    for (int i = 0; i < 8; i++)
        #pragma unroll
        for (int p = 0; p < 4; p++) {
            float2 v = unpack2(acc[i][p]);
            hf[i][2 * p]     = 0.5f * v.x * (1.0f + erff(v.x * inv_sqrt2));
            hf[i][2 * p + 1] = 0.5f * v.y * (1.0f + erff(v.y * inv_sqrt2));
        }

    __syncthreads();   // sT + s_w reads done

    // reload weights with w2; store h k-major into sT
    #pragma unroll
    for (int i = tid; i < DIM * DIM; i += 128) s_w[i] = w2[i];
    #pragma unroll
    for (int j = 0; j < 8; j++) {
        float4 h0 = make_float4(hf[0][j], hf[1][j], hf[2][j], hf[3][j]);
        float4 h1 = make_float4(hf[4][j], hf[5][j], hf[6][j], hf[7][j]);
        *reinterpret_cast<float4*>(&sT[(tc * 8 + j) * FT + tn * 8])     = h0;
        *reinterpret_cast<float4*>(&sT[(tc * 8 + j) * FT + tn * 8 + 4]) = h1;
    }
    __syncthreads();

    // ---- GEMM2: out = h @ w2 + b2 ----
    u64 acc2[8][4];
    {
        float4 bj0 = __ldg((const float4*)(b2 + tc * 8));
        float4 bj1 = __ldg((const float4*)(b2 + tc * 8 + 4));
        u64 bb[4] = {pack2(bj0.x, bj0.y), pack2(bj0.z, bj0.w),
                     pack2(bj1.x, bj1.y), pack2(bj1.z, bj1.w)};
        #pragma unroll
        for (int i = 0; i < 8; i++)
            #pragma unroll
            for (int p = 0; p < 4; p++) acc2[i][p] = bb[p];
    }

    #pragma unroll 4
    for (int k = 0; k < DIM; k++) {
        float4 a0 = *reinterpret_cast<const float4*>(&sT[k * FT + tn * 8]);
        float4 a1 = *reinterpret_cast<const float4*>(&sT[k * FT + tn * 8 + 4]);
        const u64* wrow = reinterpret_cast<const u64*>(&s_w[k * DIM + tc * 8]);
        ulonglong2 wp0 = *reinterpret_cast<const ulonglong2*>(wrow);
        ulonglong2 wp1 = *reinterpret_cast<const ulonglong2*>(wrow + 2);
        float a[8] = {a0.x, a0.y, a0.z, a0.w, a1.x, a1.y, a1.z, a1.w};
        #pragma unroll
        for (int i = 0; i < 8; i++) {
            u64 ap = pack2(a[i], a[i]);
            FMA2(acc2[i][0], ap, wp0.x);
            FMA2(acc2[i][1], ap, wp0.y);
            FMA2(acc2[i][2], ap, wp1.x);
            FMA2(acc2[i][3], ap, wp1.y);
        }
    }

    // write output: packed pairs are contiguous along cols
    #pragma unroll
    for (int i = 0; i < 8; i++) {
        int node = base + tn * 8 + i;
        if (node < N_NODES) {
            u64* p = reinterpret_cast<u64*>(out + (size_t)node * DIM + tc * 8);
            ulonglong2 v0; v0.x = acc2[i][0]; v0.y = acc2[i][1];
            ulonglong2 v1; v1.x = acc2[i][2]; v1.y = acc2[i][3];
            *reinterpret_cast<ulonglong2*>(p)     = v0;
            *reinterpret_cast<ulonglong2*>(p + 2) = v1;
        }
    }
}

// ---------------------------------------------------------------------------
// Launcher. Inputs: x, edge_src, edge_dst, w1, b1, w2, b2
// ---------------------------------------------------------------------------
extern "C" void kernel_launch(void* const* d_in, const int* in_sizes, int n_in,
                              void* d_out, int out_size) {
    const float* x   = (const float*)d_in[0];
    const int*   src = (const int*)d_in[1];
    const int*   dst = (const int*)d_in[2];
    const float* w1  = (const float*)d_in[3];
    const float* b1  = (const float*)d_in[4];
    const float* w2  = (const float*)d_in[5];
    const float* b2  = (const float*)d_in[6];
    float* out = (float*)d_out;

    zero_kernel<<<NP, 256>>>();
    hist_kernel<<<(N_EDGES / 4 + 255) / 256, 256>>>(src, dst);
    scan_kernel<<<NP, 256>>>();
    fill_kernel<<<(N_EDGES / 4 + 255) / 256, 256>>>(src, dst);
    gather_kernel<<<(N_NODES * 32 + 255) / 256, 256>>>(x);
    ffn_kernel<<<(N_NODES + FT - 1) / FT, 128>>>(w1, b1, w2, b2, out);
}

// round 7
// speedup vs baseline: 1.0279x; 1.0279x over previous
#include <cuda_runtime.h>
#include <math.h>

#define N_NODES 50000
#define N_EDGES 800000
#define DIM 64
#define FT 128   // nodes per FFN block
#define NP 196   // ceil(N_NODES / 256)

typedef unsigned long long u64;

__device__ __forceinline__ u64 pack2(float lo, float hi) {
    u64 d;
    asm("mov.b64 %0, {%1, %2};"
        : "=l"(d) : "r"(__float_as_uint(lo)), "r"(__float_as_uint(hi)));
    return d;
}
__device__ __forceinline__ float2 unpack2(u64 v) {
    unsigned lo, hi;
    asm("mov.b64 {%0, %1}, %2;" : "=r"(lo), "=r"(hi) : "l"(v));
    return make_float2(__uint_as_float(lo), __uint_as_float(hi));
}
#define FMA2(d, a, b) asm("fma.rn.f32x2 %0, %1, %2, %0;" : "+l"(d) : "l"(a), "l"(b))

// Scratch (device globals)
__device__ int   g_out_cnt[N_NODES];
__device__ int   g_in_cnt[N_NODES];
__device__ int   g_row_start[N_NODES];
__device__ int   g_cursor[N_NODES];
__device__ float g_rs[N_NODES];        // rsqrt(out_deg)
__device__ int   g_perm[N_EDGES];
__device__ float g_agg[(size_t)N_NODES * DIM];

// ---------------------------------------------------------------------------
// 0) Zero counters
// ---------------------------------------------------------------------------
__global__ void zero_kernel() {
    int i = blockIdx.x * blockDim.x + threadIdx.x;
    if (i < N_NODES) {
        g_out_cnt[i] = 0;
        g_in_cnt[i]  = 0;
    }
}

// ---------------------------------------------------------------------------
// 1) Histogram: 1 edge per thread (max MLP for atomic latency hiding)
// ---------------------------------------------------------------------------
__global__ void hist_kernel(const int* __restrict__ src,
                            const int* __restrict__ dst) {
    int i = blockIdx.x * blockDim.x + threadIdx.x;
    if (i < N_EDGES) {
        atomicAdd(&g_out_cnt[src[i]], 1);
        atomicAdd(&g_in_cnt[dst[i]], 1);
    }
}

// ---------------------------------------------------------------------------
// 2) Single-kernel exclusive scan of in_cnt (+ rs table from out_cnt).
//    Block b redundantly sums in_cnt[0..256b), then local shuffle scan.
// ---------------------------------------------------------------------------
__global__ void __launch_bounds__(256) scan_kernel() {
    __shared__ int ws1[8], ws2[8];
    __shared__ int s_base;
    const int t = threadIdx.x, lane = t & 31, w = t >> 5;
    const int b = blockIdx.x;

    int pre = 0;
    for (int i = t; i < b * 256; i += 256) pre += g_in_cnt[i];
    #pragma unroll
    for (int off = 16; off > 0; off >>= 1)
        pre += __shfl_down_sync(0xffffffffu, pre, off);
    if (lane == 0) ws1[w] = pre;
    __syncthreads();
    if (t == 0) {
        int s = 0;
        #pragma unroll
        for (int k = 0; k < 8; k++) s += ws1[k];
        s_base = s;
    }

    int i = b * 256 + t;
    int c = (i < N_NODES) ? g_in_cnt[i] : 0;
    int v = c;
    #pragma unroll
    for (int off = 1; off < 32; off <<= 1) {
        int n = __shfl_up_sync(0xffffffffu, v, off);
        if (lane >= off) v += n;
    }
    if (lane == 31) ws2[w] = v;
    __syncthreads();
    if (w == 0 && lane < 8) {
        int s = ws2[lane];
        #pragma unroll
        for (int off = 1; off < 8; off <<= 1) {
            int n = __shfl_up_sync(0x000000ffu, s, off);
            if (lane >= off) s += n;
        }
        ws2[lane] = s;
    }
    __syncthreads();
    if (i < N_NODES) {
        int start = s_base + (v - c) + ((w > 0) ? ws2[w - 1] : 0);
        g_row_start[i] = start;
        g_cursor[i]    = start;
        g_rs[i] = rsqrtf((float)g_out_cnt[i]);   // inf if 0; never read for deg-0 srcs
    }
}

// ---------------------------------------------------------------------------
// 3) Fill: perm[cursor[dst]++] = src   (4B record, 1 edge per thread)
// ---------------------------------------------------------------------------
__global__ void fill_kernel(const int* __restrict__ src,
                            const int* __restrict__ dst) {
    int i = blockIdx.x * blockDim.x + threadIdx.x;
    if (i < N_EDGES) {
        int pos = atomicAdd(&g_cursor[dst[i]], 1);
        g_perm[pos] = src[i];
    }
}

// ---------------------------------------------------------------------------
// 4) Gather-aggregate: warp per dst node, register accumulation, single write.
// ---------------------------------------------------------------------------
__global__ void __launch_bounds__(256) gather_kernel(const float* __restrict__ x) {
    int node = (blockIdx.x * blockDim.x + threadIdx.x) >> 5;
    if (node >= N_NODES) return;
    const int lane = threadIdx.x & 31;

    const int deg   = __ldg(g_in_cnt + node);
    const int start = __ldg(g_row_start + node);
    const int end   = start + deg;

    float acc0 = 0.0f, acc1 = 0.0f;
    int j = start;
    for (; j + 4 <= end; j += 4) {
        int s0 = __ldg(g_perm + j);
        int s1 = __ldg(g_perm + j + 1);
        int s2 = __ldg(g_perm + j + 2);
        int s3 = __ldg(g_perm + j + 3);
        float n0 = __ldg(g_rs + s0);
        float n1 = __ldg(g_rs + s1);
        float n2 = __ldg(g_rs + s2);
        float n3 = __ldg(g_rs + s3);
        const float* p0 = x + (size_t)s0 * DIM;
        const float* p1 = x + (size_t)s1 * DIM;
        const float* p2 = x + (size_t)s2 * DIM;
        const float* p3 = x + (size_t)s3 * DIM;
        acc0 = fmaf(__ldg(p0 + lane),      n0, acc0);
        acc1 = fmaf(__ldg(p0 + lane + 32), n0, acc1);
        acc0 = fmaf(__ldg(p1 + lane),      n1, acc0);
        acc1 = fmaf(__ldg(p1 + lane + 32), n1, acc1);
        acc0 = fmaf(__ldg(p2 + lane),      n2, acc0);
        acc1 = fmaf(__ldg(p2 + lane + 32), n2, acc1);
        acc0 = fmaf(__ldg(p3 + lane),      n3, acc0);
        acc1 = fmaf(__ldg(p3 + lane + 32), n3, acc1);
    }
    for (; j < end; j++) {
        int s0 = __ldg(g_perm + j);
        float n0 = __ldg(g_rs + s0);
        const float* p0 = x + (size_t)s0 * DIM;
        acc0 = fmaf(__ldg(p0 + lane),      n0, acc0);
        acc1 = fmaf(__ldg(p0 + lane + 32), n0, acc1);
    }

    float rs_in = (deg > 0) ? rsqrtf((float)deg) : 0.0f;
    g_agg[(size_t)node * DIM + lane]      = acc0 * rs_in;
    g_agg[(size_t)node * DIM + lane + 32] = acc1 * rs_in;
}

// ---------------------------------------------------------------------------
// 5) FFN with packed f32x2 FMA. Block = 128 nodes x 64 cols, 128 threads.
// ---------------------------------------------------------------------------
__global__ void __launch_bounds__(128) ffn_kernel(const float* __restrict__ w1,
                                                  const float* __restrict__ b1,
                                                  const float* __restrict__ w2,
                                                  const float* __restrict__ b2,
                                                  float* __restrict__ out) {
    __shared__ float sT[DIM * FT];     // [k][node] 32KB, reused for h
    __shared__ float s_w[DIM * DIM];   // 16KB, w1 then w2

    const int tid  = threadIdx.x;
    const int base = blockIdx.x * FT;
    const int tn   = tid & 15;
    const int tc   = tid >> 4;

    #pragma unroll
    for (int i = tid; i < DIM * DIM; i += 128) s_w[i] = w1[i];

    {
        const int node = base + tid;
        #pragma unroll
        for (int k4 = 0; k4 < 16; k4++) {
            float4 v = make_float4(0.f, 0.f, 0.f, 0.f);
            if (node < N_NODES)
                v = *reinterpret_cast<const float4*>(g_agg + (size_t)node * DIM + k4 * 4);
            sT[(k4 * 4 + 0) * FT + tid] = v.x;
            sT[(k4 * 4 + 1) * FT + tid] = v.y;
            sT[(k4 * 4 + 2) * FT + tid] = v.z;
            sT[(k4 * 4 + 3) * FT + tid] = v.w;
        }
    }
    __syncthreads();

    u64 acc[8][4];
    {
        float4 bj0 = __ldg((const float4*)(b1 + tc * 8));
        float4 bj1 = __ldg((const float4*)(b1 + tc * 8 + 4));
        u64 bb[4] = {pack2(bj0.x, bj0.y), pack2(bj0.z, bj0.w),
                     pack2(bj1.x, bj1.y), pack2(bj1.z, bj1.w)};
        #pragma unroll
        for (int i = 0; i < 8; i++)
            #pragma unroll
            for (int p = 0; p < 4; p++) acc[i][p] = bb[p];
    }

    #pragma unroll 4
    for (int k = 0; k < DIM; k++) {
        float4 a0 = *reinterpret_cast<const float4*>(&sT[k * FT + tn * 8]);
        float4 a1 = *reinterpret_cast<const float4*>(&sT[k * FT + tn * 8 + 4]);
        const u64* wrow = reinterpret_cast<const u64*>(&s_w[k * DIM + tc * 8]);
        ulonglong2 wp0 = *reinterpret_cast<const ulonglong2*>(wrow);
        ulonglong2 wp1 = *reinterpret_cast<const ulonglong2*>(wrow + 2);
        float a[8] = {a0.x, a0.y, a0.z, a0.w, a1.x, a1.y, a1.z, a1.w};
        #pragma unroll
        for (int i = 0; i < 8; i++) {
            u64 ap = pack2(a[i], a[i]);
            FMA2(acc[i][0], ap, wp0.x);
            FMA2(acc[i][1], ap, wp0.y);
            FMA2(acc[i][2], ap, wp1.x);
            FMA2(acc[i][3], ap, wp1.y);
        }
    }

    float hf[8][8];
    const float inv_sqrt2 = 0.70710678118654752f;
    #pragma unroll
    for (int i = 0; i < 8; i++)
        #pragma unroll
        for (int p = 0; p < 4; p++) {
            float2 v = unpack2(acc[i][p]);
            hf[i][2 * p]     = 0.5f * v.x * (1.0f + erff(v.x * inv_sqrt2));
            hf[i][2 * p + 1] = 0.5f * v.y * (1.0f + erff(v.y * inv_sqrt2));
        }

    __syncthreads();

    #pragma unroll
    for (int i = tid; i < DIM * DIM; i += 128) s_w[i] = w2[i];
    #pragma unroll
    for (int j = 0; j < 8; j++) {
        float4 h0 = make_float4(hf[0][j], hf[1][j], hf[2][j], hf[3][j]);
        float4 h1 = make_float4(hf[4][j], hf[5][j], hf[6][j], hf[7][j]);
        *reinterpret_cast<float4*>(&sT[(tc * 8 + j) * FT + tn * 8])     = h0;
        *reinterpret_cast<float4*>(&sT[(tc * 8 + j) * FT + tn * 8 + 4]) = h1;
    }
    __syncthreads();

    u64 acc2[8][4];
    {
        float4 bj0 = __ldg((const float4*)(b2 + tc * 8));
        float4 bj1 = __ldg((const float4*)(b2 + tc * 8 + 4));
        u64 bb[4] = {pack2(bj0.x, bj0.y), pack2(bj0.z, bj0.w),
                     pack2(bj1.x, bj1.y), pack2(bj1.z, bj1.w)};
        #pragma unroll
        for (int i = 0; i < 8; i++)
            #pragma unroll
            for (int p = 0; p < 4; p++) acc2[i][p] = bb[p];
    }

    #pragma unroll 4
    for (int k = 0; k < DIM; k++) {
        float4 a0 = *reinterpret_cast<const float4*>(&sT[k * FT + tn * 8]);
        float4 a1 = *reinterpret_cast<const float4*>(&sT[k * FT + tn * 8 + 4]);
        const u64* wrow = reinterpret_cast<const u64*>(&s_w[k * DIM + tc * 8]);
        ulonglong2 wp0 = *reinterpret_cast<const ulonglong2*>(wrow);
        ulonglong2 wp1 = *reinterpret_cast<const ulonglong2*>(wrow + 2);
        float a[8] = {a0.x, a0.y, a0.z, a0.w, a1.x, a1.y, a1.z, a1.w};
        #pragma unroll
        for (int i = 0; i < 8; i++) {
            u64 ap = pack2(a[i], a[i]);
            FMA2(acc2[i][0], ap, wp0.x);
            FMA2(acc2[i][1], ap, wp0.y);
            FMA2(acc2[i][2], ap, wp1.x);
            FMA2(acc2[i][3], ap, wp1.y);
        }
    }

    #pragma unroll
    for (int i = 0; i < 8; i++) {
        int node = base + tn * 8 + i;
        if (node < N_NODES) {
            u64* p = reinterpret_cast<u64*>(out + (size_t)node * DIM + tc * 8);
            ulonglong2 v0; v0.x = acc2[i][0]; v0.y = acc2[i][1];
            ulonglong2 v1; v1.x = acc2[i][2]; v1.y = acc2[i][3];
            *reinterpret_cast<ulonglong2*>(p)     = v0;
            *reinterpret_cast<ulonglong2*>(p + 2) = v1;
        }
    }
}

// ---------------------------------------------------------------------------
// Launcher. Inputs: x, edge_src, edge_dst, w1, b1, w2, b2
// ---------------------------------------------------------------------------
extern "C" void kernel_launch(void* const* d_in, const int* in_sizes, int n_in,
                              void* d_out, int out_size) {
    const float* x   = (const float*)d_in[0];
    const int*   src = (const int*)d_in[1];
    const int*   dst = (const int*)d_in[2];
    const float* w1  = (const float*)d_in[3];
    const float* b1  = (const float*)d_in[4];
    const float* w2  = (const float*)d_in[5];
    const float* b2  = (const float*)d_in[6];
    float* out = (float*)d_out;

    zero_kernel<<<NP, 256>>>();
    hist_kernel<<<(N_EDGES + 255) / 256, 256>>>(src, dst);
    scan_kernel<<<NP, 256>>>();
    fill_kernel<<<(N_EDGES + 255) / 256, 256>>>(src, dst);
    gather_kernel<<<(N_NODES * 32 + 255) / 256, 256>>>(x);
    ffn_kernel<<<(N_NODES + FT - 1) / FT, 128>>>(w1, b1, w2, b2, out);
}

// round 8
// speedup vs baseline: 1.0283x; 1.0004x over previous
#include <cuda_runtime.h>
#include <math.h>

#define N_NODES 50000
#define N_EDGES 800000
#define DIM 64
#define FT 128   // nodes per FFN block
#define NP 196   // ceil(N_NODES / 256)

// Scratch (device globals)
__device__ int    g_out_cnt[N_NODES];
__device__ int    g_in_cnt[N_NODES];
__device__ int    g_row_start[N_NODES];
__device__ int    g_rank[N_EDGES];      // rank of edge within its dst bucket
__device__ float2 g_edata[N_EDGES];     // (src_idx bits, rsqrt(out_deg[src]))
__device__ float  g_agg[(size_t)N_NODES * DIM];

// ---------------------------------------------------------------------------
// 0) Zero counters
// ---------------------------------------------------------------------------
__global__ void zero_kernel() {
    int i = blockIdx.x * blockDim.x + threadIdx.x;
    if (i < N_NODES) {
        g_out_cnt[i] = 0;
        g_in_cnt[i]  = 0;
    }
}

// ---------------------------------------------------------------------------
// 1) Histogram + rank capture: the atomic return value IS the edge's rank
//    within its destination bucket. Stored coalesced by edge id.
// ---------------------------------------------------------------------------
__global__ void hist_kernel(const int* __restrict__ src,
                            const int* __restrict__ dst) {
    int i = blockIdx.x * blockDim.x + threadIdx.x;
    if (i < N_EDGES) {
        atomicAdd(&g_out_cnt[src[i]], 1);
        g_rank[i] = atomicAdd(&g_in_cnt[dst[i]], 1);
    }
}

// ---------------------------------------------------------------------------
// 2) Single-kernel exclusive scan of in_cnt: block b redundantly sums
//    in_cnt[0..256b), then local shuffle scan. No cross-block sync.
// ---------------------------------------------------------------------------
__global__ void __launch_bounds__(256) scan_kernel() {
    __shared__ int ws1[8], ws2[8];
    __shared__ int s_base;
    const int t = threadIdx.x, lane = t & 31, w = t >> 5;
    const int b = blockIdx.x;

    int pre = 0;
    for (int i = t; i < b * 256; i += 256) pre += g_in_cnt[i];
    #pragma unroll
    for (int off = 16; off > 0; off >>= 1)
        pre += __shfl_down_sync(0xffffffffu, pre, off);
    if (lane == 0) ws1[w] = pre;
    __syncthreads();
    if (t == 0) {
        int s = 0;
        #pragma unroll
        for (int k = 0; k < 8; k++) s += ws1[k];
        s_base = s;
    }

    int i = b * 256 + t;
    int c = (i < N_NODES) ? g_in_cnt[i] : 0;
    int v = c;
    #pragma unroll
    for (int off = 1; off < 32; off <<= 1) {
        int n = __shfl_up_sync(0xffffffffu, v, off);
        if (lane >= off) v += n;
    }
    if (lane == 31) ws2[w] = v;
    __syncthreads();
    if (w == 0 && lane < 8) {
        int s = ws2[lane];
        #pragma unroll
        for (int off = 1; off < 8; off <<= 1) {
            int n = __shfl_up_sync(0x000000ffu, s, off);
            if (lane >= off) s += n;
        }
        ws2[lane] = s;
    }
    __syncthreads();
    if (i < N_NODES)
        g_row_start[i] = s_base + (v - c) + ((w > 0) ? ws2[w - 1] : 0);
}

// ---------------------------------------------------------------------------
// 3) Fill (atomic-free): pos = row_start[dst] + rank[i]
// ---------------------------------------------------------------------------
__global__ void fill_kernel(const int* __restrict__ src,
                            const int* __restrict__ dst) {
    int i = blockIdx.x * blockDim.x + threadIdx.x;
    if (i < N_EDGES) {
        int s = src[i];
        int d = dst[i];
        float rs = rsqrtf((float)__ldg(g_out_cnt + s));
        int pos = __ldg(g_row_start + d) + g_rank[i];
        g_edata[pos] = make_float2(__int_as_float(s), rs);
    }
}

// ---------------------------------------------------------------------------
// 4) Gather-aggregate: warp per dst node, register accumulation, single write.
//    (round-5 known-good shape: one 8B edata load carries src + rs)
// ---------------------------------------------------------------------------
__global__ void __launch_bounds__(256) gather_kernel(const float* __restrict__ x) {
    int node = (blockIdx.x * blockDim.x + threadIdx.x) >> 5;
    if (node >= N_NODES) return;
    const int lane = threadIdx.x & 31;

    const int deg   = __ldg(g_in_cnt + node);
    const int start = __ldg(g_row_start + node);
    const int end   = start + deg;

    float acc0 = 0.0f, acc1 = 0.0f;
    int j = start;
    for (; j + 4 <= end; j += 4) {
        float2 e0 = __ldg(g_edata + j);
        float2 e1 = __ldg(g_edata + j + 1);
        float2 e2 = __ldg(g_edata + j + 2);
        float2 e3 = __ldg(g_edata + j + 3);
        const float* p0 = x + (size_t)__float_as_int(e0.x) * DIM;
        const float* p1 = x + (size_t)__float_as_int(e1.x) * DIM;
        const float* p2 = x + (size_t)__float_as_int(e2.x) * DIM;
        const float* p3 = x + (size_t)__float_as_int(e3.x) * DIM;
        acc0 = fmaf(__ldg(p0 + lane),      e0.y, acc0);
        acc1 = fmaf(__ldg(p0 + lane + 32), e0.y, acc1);
        acc0 = fmaf(__ldg(p1 + lane),      e1.y, acc0);
        acc1 = fmaf(__ldg(p1 + lane + 32), e1.y, acc1);
        acc0 = fmaf(__ldg(p2 + lane),      e2.y, acc0);
        acc1 = fmaf(__ldg(p2 + lane + 32), e2.y, acc1);
        acc0 = fmaf(__ldg(p3 + lane),      e3.y, acc0);
        acc1 = fmaf(__ldg(p3 + lane + 32), e3.y, acc1);
    }
    for (; j < end; j++) {
        float2 e0 = __ldg(g_edata + j);
        const float* p0 = x + (size_t)__float_as_int(e0.x) * DIM;
        acc0 = fmaf(__ldg(p0 + lane),      e0.y, acc0);
        acc1 = fmaf(__ldg(p0 + lane + 32), e0.y, acc1);
    }

    float rs_in = (deg > 0) ? rsqrtf((float)deg) : 0.0f;
    g_agg[(size_t)node * DIM + lane]      = acc0 * rs_in;
    g_agg[(size_t)node * DIM + lane + 32] = acc1 * rs_in;
}

// ---------------------------------------------------------------------------
// 5) FFN (round-5 scalar shape): 128 nodes x 64 cols per block, 128 threads,
//    8x8 thread tile, weight buffer reused (w1 then w2).
// ---------------------------------------------------------------------------
__global__ void __launch_bounds__(128) ffn_kernel(const float* __restrict__ w1,
                                                  const float* __restrict__ b1,
                                                  const float* __restrict__ w2,
                                                  const float* __restrict__ b2,
                                                  float* __restrict__ out) {
    __shared__ float sT[DIM * FT];     // [k][node] 32KB, reused for h
    __shared__ float s_w[DIM * DIM];   // 16KB, w1 then w2

    const int tid  = threadIdx.x;
    const int base = blockIdx.x * FT;
    const int tn   = tid & 15;
    const int tc   = tid >> 4;

    #pragma unroll
    for (int i = tid; i < DIM * DIM; i += 128) s_w[i] = w1[i];

    {
        const int node = base + tid;
        #pragma unroll
        for (int k4 = 0; k4 < 16; k4++) {
            float4 v = make_float4(0.f, 0.f, 0.f, 0.f);
            if (node < N_NODES)
                v = *reinterpret_cast<const float4*>(g_agg + (size_t)node * DIM + k4 * 4);
            sT[(k4 * 4 + 0) * FT + tid] = v.x;
            sT[(k4 * 4 + 1) * FT + tid] = v.y;
            sT[(k4 * 4 + 2) * FT + tid] = v.z;
            sT[(k4 * 4 + 3) * FT + tid] = v.w;
        }
    }
    __syncthreads();

    // ---- GEMM1 ----
    float acc[8][8];
    {
        float4 bj0 = __ldg((const float4*)(b1 + tc * 8));
        float4 bj1 = __ldg((const float4*)(b1 + tc * 8 + 4));
        #pragma unroll
        for (int i = 0; i < 8; i++) {
            acc[i][0] = bj0.x; acc[i][1] = bj0.y; acc[i][2] = bj0.z; acc[i][3] = bj0.w;
            acc[i][4] = bj1.x; acc[i][5] = bj1.y; acc[i][6] = bj1.z; acc[i][7] = bj1.w;
        }
    }

    #pragma unroll 4
    for (int k = 0; k < DIM; k++) {
        float4 a0 = *reinterpret_cast<const float4*>(&sT[k * FT + tn * 8]);
        float4 a1 = *reinterpret_cast<const float4*>(&sT[k * FT + tn * 8 + 4]);
        float4 wv0 = *reinterpret_cast<const float4*>(&s_w[k * DIM + tc * 8]);
        float4 wv1 = *reinterpret_cast<const float4*>(&s_w[k * DIM + tc * 8 + 4]);
        float a[8] = {a0.x, a0.y, a0.z, a0.w, a1.x, a1.y, a1.z, a1.w};
        float w[8] = {wv0.x, wv0.y, wv0.z, wv0.w, wv1.x, wv1.y, wv1.z, wv1.w};
        #pragma unroll
        for (int i = 0; i < 8; i++)
            #pragma unroll
            for (int j = 0; j < 8; j++)
                acc[i][j] = fmaf(a[i], w[j], acc[i][j]);
    }

    // exact GELU
    const float inv_sqrt2 = 0.70710678118654752f;
    #pragma unroll
    for (int i = 0; i < 8; i++)
        #pragma unroll
        for (int j = 0; j < 8; j++) {
            float h = acc[i][j];
            acc[i][j] = 0.5f * h * (1.0f + erff(h * inv_sqrt2));
        }

    __syncthreads();

    #pragma unroll
    for (int i = tid; i < DIM * DIM; i += 128) s_w[i] = w2[i];
    #pragma unroll
    for (int j = 0; j < 8; j++) {
        float4 h0 = make_float4(acc[0][j], acc[1][j], acc[2][j], acc[3][j]);
        float4 h1 = make_float4(acc[4][j], acc[5][j], acc[6][j], acc[7][j]);
        *reinterpret_cast<float4*>(&sT[(tc * 8 + j) * FT + tn * 8])     = h0;
        *reinterpret_cast<float4*>(&sT[(tc * 8 + j) * FT + tn * 8 + 4]) = h1;
    }
    __syncthreads();

    // ---- GEMM2 ----
    float acc2[8][8];
    {
        float4 bj0 = __ldg((const float4*)(b2 + tc * 8));
        float4 bj1 = __ldg((const float4*)(b2 + tc * 8 + 4));
        #pragma unroll
        for (int i = 0; i < 8; i++) {
            acc2[i][0] = bj0.x; acc2[i][1] = bj0.y; acc2[i][2] = bj0.z; acc2[i][3] = bj0.w;
            acc2[i][4] = bj1.x; acc2[i][5] = bj1.y; acc2[i][6] = bj1.z; acc2[i][7] = bj1.w;
        }
    }

    #pragma unroll 4
    for (int k = 0; k < DIM; k++) {
        float4 a0 = *reinterpret_cast<const float4*>(&sT[k * FT + tn * 8]);
        float4 a1 = *reinterpret_cast<const float4*>(&sT[k * FT + tn * 8 + 4]);
        float4 wv0 = *reinterpret_cast<const float4*>(&s_w[k * DIM + tc * 8]);
        float4 wv1 = *reinterpret_cast<const float4*>(&s_w[k * DIM + tc * 8 + 4]);
        float a[8] = {a0.x, a0.y, a0.z, a0.w, a1.x, a1.y, a1.z, a1.w};
        float w[8] = {wv0.x, wv0.y, wv0.z, wv0.w, wv1.x, wv1.y, wv1.z, wv1.w};
        #pragma unroll
        for (int i = 0; i < 8; i++)
            #pragma unroll
            for (int j = 0; j < 8; j++)
                acc2[i][j] = fmaf(a[i], w[j], acc2[i][j]);
    }

    #pragma unroll
    for (int i = 0; i < 8; i++) {
        int node = base + tn * 8 + i;
        if (node < N_NODES) {
            float4 v0 = make_float4(acc2[i][0], acc2[i][1], acc2[i][2], acc2[i][3]);
            float4 v1 = make_float4(acc2[i][4], acc2[i][5], acc2[i][6], acc2[i][7]);
            float* p = out + (size_t)node * DIM + tc * 8;
            *reinterpret_cast<float4*>(p)     = v0;
            *reinterpret_cast<float4*>(p + 4) = v1;
        }
    }
}

// ---------------------------------------------------------------------------
// Launcher. Inputs: x, edge_src, edge_dst, w1, b1, w2, b2
// ---------------------------------------------------------------------------
extern "C" void kernel_launch(void* const* d_in, const int* in_sizes, int n_in,
                              void* d_out, int out_size) {
    const float* x   = (const float*)d_in[0];
    const int*   src = (const int*)d_in[1];
    const int*   dst = (const int*)d_in[2];
    const float* w1  = (const float*)d_in[3];
    const float* b1  = (const float*)d_in[4];
    const float* w2  = (const float*)d_in[5];
    const float* b2  = (const float*)d_in[6];
    float* out = (float*)d_out;

    zero_kernel<<<NP, 256>>>();
    hist_kernel<<<(N_EDGES + 255) / 256, 256>>>(src, dst);
    scan_kernel<<<NP, 256>>>();
    fill_kernel<<<(N_EDGES + 255) / 256, 256>>>(src, dst);
    gather_kernel<<<(N_NODES * 32 + 255) / 256, 256>>>(x);
    ffn_kernel<<<(N_NODES + FT - 1) / FT, 128>>>(w1, b1, w2, b2, out);
}

// round 9
// speedup vs baseline: 1.2066x; 1.1733x over previous
#include <cuda_runtime.h>
#include <math.h>

#define N_NODES 50000
#define N_EDGES 800000
#define DIM 64
#define NP 196   // ceil(N_NODES / 256)

// Scratch (device globals)
__device__ int    g_out_cnt[N_NODES];
__device__ int    g_in_cnt[N_NODES];
__device__ int    g_row_start[N_NODES];
__device__ int    g_rank[N_EDGES];      // rank of edge within its dst bucket
__device__ float2 g_edata[N_EDGES];     // (src_idx bits, rsqrt(out_deg[src]))
__device__ float  g_agg[(size_t)N_NODES * DIM];

__device__ __forceinline__ unsigned f2tf32(float f) {
    unsigned u;
    asm("cvt.rna.tf32.f32 %0, %1;" : "=r"(u) : "f"(f));
    return u;
}

#define MMA_TF32(c, a0, a1, a2, a3, b0, b1)                                   \
    asm volatile("mma.sync.aligned.m16n8k8.row.col.f32.tf32.tf32.f32 "        \
                 "{%0,%1,%2,%3}, {%4,%5,%6,%7}, {%8,%9}, {%0,%1,%2,%3};"      \
                 : "+f"(c[0]), "+f"(c[1]), "+f"(c[2]), "+f"(c[3])             \
                 : "r"(a0), "r"(a1), "r"(a2), "r"(a3), "r"(b0), "r"(b1))

// ---------------------------------------------------------------------------
// 0) Zero counters
// ---------------------------------------------------------------------------
__global__ void zero_kernel() {
    int i = blockIdx.x * blockDim.x + threadIdx.x;
    if (i < N_NODES) {
        g_out_cnt[i] = 0;
        g_in_cnt[i]  = 0;
    }
}

// ---------------------------------------------------------------------------
// 1) Histogram + rank capture (atomic return value = in-bucket rank)
// ---------------------------------------------------------------------------
__global__ void hist_kernel(const int* __restrict__ src,
                            const int* __restrict__ dst) {
    int i = blockIdx.x * blockDim.x + threadIdx.x;
    if (i < N_EDGES) {
        atomicAdd(&g_out_cnt[src[i]], 1);
        g_rank[i] = atomicAdd(&g_in_cnt[dst[i]], 1);
    }
}

// ---------------------------------------------------------------------------
// 2) Single-kernel exclusive scan of in_cnt (redundant prefix per block)
// ---------------------------------------------------------------------------
__global__ void __launch_bounds__(256) scan_kernel() {
    __shared__ int ws1[8], ws2[8];
    __shared__ int s_base;
    const int t = threadIdx.x, lane = t & 31, w = t >> 5;
    const int b = blockIdx.x;

    int pre = 0;
    for (int i = t; i < b * 256; i += 256) pre += g_in_cnt[i];
    #pragma unroll
    for (int off = 16; off > 0; off >>= 1)
        pre += __shfl_down_sync(0xffffffffu, pre, off);
    if (lane == 0) ws1[w] = pre;
    __syncthreads();
    if (t == 0) {
        int s = 0;
        #pragma unroll
        for (int k = 0; k < 8; k++) s += ws1[k];
        s_base = s;
    }

    int i = b * 256 + t;
    int c = (i < N_NODES) ? g_in_cnt[i] : 0;
    int v = c;
    #pragma unroll
    for (int off = 1; off < 32; off <<= 1) {
        int n = __shfl_up_sync(0xffffffffu, v, off);
        if (lane >= off) v += n;
    }
    if (lane == 31) ws2[w] = v;
    __syncthreads();
    if (w == 0 && lane < 8) {
        int s = ws2[lane];
        #pragma unroll
        for (int off = 1; off < 8; off <<= 1) {
            int n = __shfl_up_sync(0x000000ffu, s, off);
            if (lane >= off) s += n;
        }
        ws2[lane] = s;
    }
    __syncthreads();
    if (i < N_NODES)
        g_row_start[i] = s_base + (v - c) + ((w > 0) ? ws2[w - 1] : 0);
}

// ---------------------------------------------------------------------------
// 3) Fill (atomic-free): pos = row_start[dst] + rank[i]
// ---------------------------------------------------------------------------
__global__ void fill_kernel(const int* __restrict__ src,
                            const int* __restrict__ dst) {
    int i = blockIdx.x * blockDim.x + threadIdx.x;
    if (i < N_EDGES) {
        int s = src[i];
        int d = dst[i];
        float rs = rsqrtf((float)__ldg(g_out_cnt + s));
        int pos = __ldg(g_row_start + d) + g_rank[i];
        g_edata[pos] = make_float2(__int_as_float(s), rs);
    }
}

// ---------------------------------------------------------------------------
// 4) Gather-aggregate: warp per dst node, register accumulation, single write.
// ---------------------------------------------------------------------------
__global__ void __launch_bounds__(256) gather_kernel(const float* __restrict__ x) {
    int node = (blockIdx.x * blockDim.x + threadIdx.x) >> 5;
    if (node >= N_NODES) return;
    const int lane = threadIdx.x & 31;

    const int deg   = __ldg(g_in_cnt + node);
    const int start = __ldg(g_row_start + node);
    const int end   = start + deg;

    float acc0 = 0.0f, acc1 = 0.0f;
    int j = start;
    for (; j + 4 <= end; j += 4) {
        float2 e0 = __ldg(g_edata + j);
        float2 e1 = __ldg(g_edata + j + 1);
        float2 e2 = __ldg(g_edata + j + 2);
        float2 e3 = __ldg(g_edata + j + 3);
        const float* p0 = x + (size_t)__float_as_int(e0.x) * DIM;
        const float* p1 = x + (size_t)__float_as_int(e1.x) * DIM;
        const float* p2 = x + (size_t)__float_as_int(e2.x) * DIM;
        const float* p3 = x + (size_t)__float_as_int(e3.x) * DIM;
        acc0 = fmaf(__ldg(p0 + lane),      e0.y, acc0);
        acc1 = fmaf(__ldg(p0 + lane + 32), e0.y, acc1);
        acc0 = fmaf(__ldg(p1 + lane),      e1.y, acc0);
        acc1 = fmaf(__ldg(p1 + lane + 32), e1.y, acc1);
        acc0 = fmaf(__ldg(p2 + lane),      e2.y, acc0);
        acc1 = fmaf(__ldg(p2 + lane + 32), e2.y, acc1);
        acc0 = fmaf(__ldg(p3 + lane),      e3.y, acc0);
        acc1 = fmaf(__ldg(p3 + lane + 32), e3.y, acc1);
    }
    for (; j < end; j++) {
        float2 e0 = __ldg(g_edata + j);
        const float* p0 = x + (size_t)__float_as_int(e0.x) * DIM;
        acc0 = fmaf(__ldg(p0 + lane),      e0.y, acc0);
        acc1 = fmaf(__ldg(p0 + lane + 32), e0.y, acc1);
    }

    float rs_in = (deg > 0) ? rsqrtf((float)deg) : 0.0f;
    g_agg[(size_t)node * DIM + lane]      = acc0 * rs_in;
    g_agg[(size_t)node * DIM + lane + 32] = acc1 * rs_in;
}

// ---------------------------------------------------------------------------
// 5) FFN on tensor cores (tf32 mma.m16n8k8, fp32 accumulate).
//    Block = 64 nodes, 128 threads (4 warps). Warp = 16-row stripe x 64 cols.
//    sA stride 68 (A-frag loads conflict-free), sW stride 72 (B-frags c-free).
// ---------------------------------------------------------------------------
#define SA_STRIDE 68
#define SW_STRIDE 72

__global__ void __launch_bounds__(128) ffn_kernel(const float* __restrict__ w1,
                                                  const float* __restrict__ b1,
                                                  const float* __restrict__ w2,
                                                  const float* __restrict__ b2,
                                                  float* __restrict__ out) {
    __shared__ unsigned sA[DIM * SA_STRIDE];   // tf32 bits: agg tile, then H
    __shared__ unsigned sW[DIM * SW_STRIDE];   // tf32 bits: w1, then w2
    __shared__ float    sB1[DIM], sB2[DIM];

    const int tid  = threadIdx.x;
    const int lane = tid & 31;
    const int warp = tid >> 5;
    const int base = blockIdx.x * 64;
    const int m0   = warp * 16;
    const int qr   = lane >> 2;   // 0..7
    const int qc   = lane & 3;    // 0..3

    // load w1 (tf32) + biases
    #pragma unroll
    for (int i = tid; i < DIM * DIM; i += 128)
        sW[(i >> 6) * SW_STRIDE + (i & 63)] = f2tf32(w1[i]);
    if (tid < DIM) { sB1[tid] = b1[tid]; sB2[tid] = b2[tid]; }

    // load agg tile (tf32): thread handles node = tid/2, k-half = (tid&1)*32
    {
        const int r  = tid >> 1;
        const int kh = (tid & 1) * 32;
        const int node = base + r;
        #pragma unroll
        for (int q = 0; q < 8; q++) {
            float4 v = make_float4(0.f, 0.f, 0.f, 0.f);
            if (node < N_NODES)
                v = *reinterpret_cast<const float4*>(g_agg + (size_t)node * DIM + kh + q * 4);
            unsigned* p = &sA[r * SA_STRIDE + kh + q * 4];
            p[0] = f2tf32(v.x); p[1] = f2tf32(v.y);
            p[2] = f2tf32(v.z); p[3] = f2tf32(v.w);
        }
    }
    __syncthreads();

    // ---- GEMM1: H = agg @ w1 + b1 ----
    float c[8][4];
    #pragma unroll
    for (int nt = 0; nt < 8; nt++) {
        float blo = sB1[nt * 8 + qc * 2];
        float bhi = sB1[nt * 8 + qc * 2 + 1];
        c[nt][0] = blo; c[nt][1] = bhi; c[nt][2] = blo; c[nt][3] = bhi;
    }

    #pragma unroll
    for (int k0 = 0; k0 < DIM; k0 += 8) {
        unsigned a0 = sA[(m0 + qr)     * SA_STRIDE + k0 + qc];
        unsigned a1 = sA[(m0 + qr + 8) * SA_STRIDE + k0 + qc];
        unsigned a2 = sA[(m0 + qr)     * SA_STRIDE + k0 + qc + 4];
        unsigned a3 = sA[(m0 + qr + 8) * SA_STRIDE + k0 + qc + 4];
        #pragma unroll
        for (int nt = 0; nt < 8; nt++) {
            unsigned bb0 = sW[(k0 + qc)     * SW_STRIDE + nt * 8 + qr];
            unsigned bb1 = sW[(k0 + qc + 4) * SW_STRIDE + nt * 8 + qr];
            MMA_TF32(c[nt], a0, a1, a2, a3, bb0, bb1);
        }
    }

    // exact GELU
    const float inv_sqrt2 = 0.70710678118654752f;
    #pragma unroll
    for (int nt = 0; nt < 8; nt++)
        #pragma unroll
        for (int r = 0; r < 4; r++) {
            float h = c[nt][r];
            c[nt][r] = 0.5f * h * (1.0f + erff(h * inv_sqrt2));
        }

    __syncthreads();   // all GEMM1 sA/sW reads complete

    // reload sW with w2 (tf32); store H (tf32) into sA
    #pragma unroll
    for (int i = tid; i < DIM * DIM; i += 128)
        sW[(i >> 6) * SW_STRIDE + (i & 63)] = f2tf32(w2[i]);
    #pragma unroll
    for (int nt = 0; nt < 8; nt++) {
        int col = nt * 8 + qc * 2;
        int row = m0 + qr;
        sA[row * SA_STRIDE + col]           = f2tf32(c[nt][0]);
        sA[row * SA_STRIDE + col + 1]       = f2tf32(c[nt][1]);
        sA[(row + 8) * SA_STRIDE + col]     = f2tf32(c[nt][2]);
        sA[(row + 8) * SA_STRIDE + col + 1] = f2tf32(c[nt][3]);
    }
    __syncthreads();

    // ---- GEMM2: out = H @ w2 + b2 ----
    float c2[8][4];
    #pragma unroll
    for (int nt = 0; nt < 8; nt++) {
        float blo = sB2[nt * 8 + qc * 2];
        float bhi = sB2[nt * 8 + qc * 2 + 1];
        c2[nt][0] = blo; c2[nt][1] = bhi; c2[nt][2] = blo; c2[nt][3] = bhi;
    }

    #pragma unroll
    for (int k0 = 0; k0 < DIM; k0 += 8) {
        unsigned a0 = sA[(m0 + qr)     * SA_STRIDE + k0 + qc];
        unsigned a1 = sA[(m0 + qr + 8) * SA_STRIDE + k0 + qc];
        unsigned a2 = sA[(m0 + qr)     * SA_STRIDE + k0 + qc + 4];
        unsigned a3 = sA[(m0 + qr + 8) * SA_STRIDE + k0 + qc + 4];
        #pragma unroll
        for (int nt = 0; nt < 8; nt++) {
            unsigned bb0 = sW[(k0 + qc)     * SW_STRIDE + nt * 8 + qr];
            unsigned bb1 = sW[(k0 + qc + 4) * SW_STRIDE + nt * 8 + qr];
            MMA_TF32(c2[nt], a0, a1, a2, a3, bb0, bb1);
        }
    }

    // write out
    #pragma unroll
    for (int nt = 0; nt < 8; nt++) {
        int col  = nt * 8 + qc * 2;
        int row0 = base + m0 + qr;
        if (row0 < N_NODES)
            *reinterpret_cast<float2*>(out + (size_t)row0 * DIM + col) =
                make_float2(c2[nt][0], c2[nt][1]);
        if (row0 + 8 < N_NODES)
            *reinterpret_cast<float2*>(out + (size_t)(row0 + 8) * DIM + col) =
                make_float2(c2[nt][2], c2[nt][3]);
    }
}

// ---------------------------------------------------------------------------
// Launcher. Inputs: x, edge_src, edge_dst, w1, b1, w2, b2
// ---------------------------------------------------------------------------
extern "C" void kernel_launch(void* const* d_in, const int* in_sizes, int n_in,
                              void* d_out, int out_size) {
    const float* x   = (const float*)d_in[0];
    const int*   src = (const int*)d_in[1];
    const int*   dst = (const int*)d_in[2];
    const float* w1  = (const float*)d_in[3];
    const float* b1  = (const float*)d_in[4];
    const float* w2  = (const float*)d_in[5];
    const float* b2  = (const float*)d_in[6];
    float* out = (float*)d_out;

    zero_kernel<<<NP, 256>>>();
    hist_kernel<<<(N_EDGES + 255) / 256, 256>>>(src, dst);
    scan_kernel<<<NP, 256>>>();
    fill_kernel<<<(N_EDGES + 255) / 256, 256>>>(src, dst);
    gather_kernel<<<(N_NODES * 32 + 255) / 256, 256>>>(x);
    ffn_kernel<<<(N_NODES + 63) / 64, 128>>>(w1, b1, w2, b2, out);
}